// round 15
// baseline (speedup 1.0000x reference)
#include <cuda_runtime.h>
#include <cuda_bf16.h>
#include <cstdint>
#include <cstddef>

// ---------------------------------------------------------------------------
// MinGRU (2 layers), B=8, S=8192, DIN=DH=256.
//   gh = x @ W^T + b; a = sigmoid(-gate); v = sigmoid(gate)*g(hidden)
//   h_t = a_t*h_{t-1} + v_t, h0 = 0.5  (linear-space equivalent of reference)
// fp32 GEMM emulated with 3 bf16 mma.sync products: Ahi*Whi + Ahi*Wlo + Alo*Whi.
// R14: convert_x and pass3_l0 fused into the gemm prologues WITHOUT work
//      duplication: each of the 4 same-m0 CTAs converts its 32 of 128 rows
//      (elementwise thanks to R13's (P,Q) form), then group-syncs via a
//      per-m0 atomic counter (reset each launch by scan_combine).
// ---------------------------------------------------------------------------

#define M_ROWS   65536
#define KDIM     256
#define BATCH    8
#define SEQ      8192
#define NCH      64
#define CHLEN    128
#define OUT1_ELEMS 16777216

#define STAGES     3
#define BK         32
#define SLOT_ELEMS (128 * 32)                // 4096 elems = 8192 B (no padding)
#define STAGE_ELEMS (4 * SLOT_ELEMS)         // Ahi, Alo, Whi, Wlo
#define SMEM_BYTES (STAGES * STAGE_ELEMS * 2)   // 98304

// swizzled element offset within a slot; col is bf16 elem 0..31, col%8==0 use
__device__ __forceinline__ int swoff(int row, int col) {
    return row * 32 + ((((col >> 3) ^ ((row >> 1) & 3)) << 3) | (col & 7));
}

// -------------------- scratch (device globals; no allocation) --------------
__device__ __nv_bfloat16 g_xhi[16777216];     // 32 MB  (A hi; x-split then h-split)
__device__ __nv_bfloat16 g_xlo[16777216];     // 32 MB  (A lo)
__device__ float2        g_av [16777216];     // 128 MB per-row chunk prefix (P,Q)
__device__ __nv_bfloat16 g_whi[2][131072];    // W hi, interleaved rows
__device__ __nv_bfloat16 g_wlo[2][131072];    // W lo
__device__ float         g_bc [2][512];       // bias, interleaved
__device__ float2        g_agg[BATCH * NCH * 256];
__device__ float         g_h0 [BATCH * NCH * 256];
__device__ int           g_cnt[2][512];       // per-m0 prologue arrival counters

// -------------------- small helpers ----------------------------------------
__device__ __forceinline__ void cp16(void* dst, const void* src) {
    uint32_t d = (uint32_t)__cvta_generic_to_shared(dst);
    asm volatile("cp.async.cg.shared.global [%0], [%1], 16;\n" :: "r"(d), "l"(src));
}
#define CP_COMMIT() asm volatile("cp.async.commit_group;\n" ::: "memory")

__device__ __forceinline__ void ldsm_x4(uint32_t (&r)[4], const void* p) {
    uint32_t a = (uint32_t)__cvta_generic_to_shared(p);
    asm volatile("ldmatrix.sync.aligned.m8n8.x4.shared.b16 {%0,%1,%2,%3}, [%4];"
                 : "=r"(r[0]), "=r"(r[1]), "=r"(r[2]), "=r"(r[3]) : "r"(a));
}

__device__ __forceinline__ void mma16816(float* c, const uint32_t* a, uint32_t b0, uint32_t b1) {
    asm volatile(
        "mma.sync.aligned.m16n8k16.row.col.f32.bf16.bf16.f32 "
        "{%0,%1,%2,%3}, {%4,%5,%6,%7}, {%8,%9}, {%0,%1,%2,%3};"
        : "+f"(c[0]), "+f"(c[1]), "+f"(c[2]), "+f"(c[3])
        : "r"(a[0]), "r"(a[1]), "r"(a[2]), "r"(a[3]), "r"(b0), "r"(b1));
}

// a = sigmoid(-gate), v = sigmoid(gate)*g(hidden)
__device__ __forceinline__ float2 av_from(float gate, float hid) {
    float e   = __expf(-fabsf(gate));
    float inv = 1.0f / (1.0f + e);
    float z, a;
    if (gate >= 0.0f) { z = inv;     a = e * inv; }
    else              { z = e * inv; a = inv;     }
    float g = (hid >= 0.0f) ? (hid + 0.5f) : (1.0f / (1.0f + __expf(-hid)));
    return make_float2(a, z * g);
}

// -------------------- weight prep -------------------------------------------
// W rows interleaved (gate_d, hidden_d) + bias, one launch.
__global__ void convert_wb_kernel(const float* __restrict__ W0, const float* __restrict__ W1,
                                  const float* __restrict__ b0, const float* __restrict__ b1) {
    int idx = blockIdx.x * blockDim.x + threadIdx.x;  // 0..263167
    if (idx < 262144) {
        int l = idx >> 17;
        int r = (idx >> 8) & 511;
        int k = idx & 255;
        const float* W = l ? W1 : W0;
        int src = (r & 1) ? (256 + (r >> 1)) : (r >> 1);
        float w = W[src * 256 + k];
        __nv_bfloat16 h = __float2bfloat16(w);
        g_whi[l][r * 256 + k] = h;
        g_wlo[l][r * 256 + k] = __float2bfloat16(w - __bfloat162float(h));
    } else {
        int j = idx - 262144;                 // 0..1023
        int l = j >> 9, n = j & 511;
        int src = (n & 1) ? (256 + (n >> 1)) : (n >> 1);
        g_bc[l][n] = (l ? b1 : b0)[src];
    }
}

// -------------------- GEMM + split prologue + prefix epilogue ----------------
// Block tile 128x128 (one scan chunk x 64 channels). 8 iterations; stage c
// holds {Ahi,Alo,Whi,Wlo} for k-chunk c (swizzled); all 3 products per chunk.
// Prologue: the 4 CTAs sharing m0 each convert 32 rows of the A operand
// (layer 0: x fp32 -> hi/lo split; layer 1: h = P*h0+Q -> hi/lo split),
// then group-sync via g_cnt[layer][m0-group].
__global__ void __launch_bounds__(256, 2)
gemm_kernel(int layer, const float* __restrict__ x, float* __restrict__ dout) {
    const __nv_bfloat16* __restrict__ Ahi = g_xhi;
    const __nv_bfloat16* __restrict__ Alo = g_xlo;
    const __nv_bfloat16* __restrict__ Whi = g_whi[layer];
    const __nv_bfloat16* __restrict__ Wlo = g_wlo[layer];
    const float* __restrict__ bc = g_bc[layer];

    extern __shared__ __align__(128) __nv_bfloat16 smem[];

    const int tid  = threadIdx.x;
    const int lane = tid & 31;
    const int warp = tid >> 5;
    const int wm   = warp & 3;   // 4 warps along M (32 rows each)
    const int wn   = warp >> 2;  // 2 warps along N (64 cols each)
    const int bx   = blockIdx.x; // 0..3 (N-block, also prologue row-slice owner)
    const int gy   = blockIdx.y; // 0..511 (m0 group)
    const int m0   = gy * 128;
    const int n0   = bx * 128;

    // ---------------- split prologue: own 32 rows of A ----------------------
    if (layer == 0) {
        // rows [bx*32, bx*32+32): x fp32 -> hi/lo split (64 float4 per row)
        for (int i = tid; i < 32 * 64; i += 256) {
            int row = bx * 32 + (i >> 6);
            int c4  = i & 63;
            size_t g4 = (size_t)(m0 + row) * 64 + c4;
            float4 v = reinterpret_cast<const float4*>(x)[g4];
            float vv[4] = {v.x, v.y, v.z, v.w};
            ushort4 hi4, lo4;
            unsigned short* hp = &hi4.x;
            unsigned short* lp = &lo4.x;
#pragma unroll
            for (int j = 0; j < 4; j++) {
                __nv_bfloat16 h = __float2bfloat16(vv[j]);
                float r = vv[j] - __bfloat162float(h);
                hp[j] = __bfloat16_as_ushort(h);
                lp[j] = __bfloat16_as_ushort(__float2bfloat16(r));
            }
            reinterpret_cast<ushort4*>(g_xhi)[g4] = hi4;
            reinterpret_cast<ushort4*>(g_xlo)[g4] = lo4;
        }
    } else {
        // rows [bx*32, bx*32+32): h = P*h0 + Q -> hi/lo split (this IS pass3_l0)
        const int b   = m0 >> 13;
        const int chk = (m0 >> 7) & 63;
        const float* h0row = g_h0 + (b * NCH + chk) * 256;
        for (int i = tid; i < 32 * 256; i += 256) {
            int row = bx * 32 + (i >> 8);
            int d   = i & 255;
            size_t idx = (size_t)(m0 + row) * 256 + d;
            float2 t = g_av[idx];
            float h = fmaf(t.x, h0row[d], t.y);
            __nv_bfloat16 hi = __float2bfloat16(h);
            g_xhi[idx] = hi;
            g_xlo[idx] = __float2bfloat16(h - __bfloat162float(hi));
            if (row == 127 && chk == NCH - 1)
                dout[OUT1_ELEMS + b * 256 + d] = h;   // layer-0 final hidden
        }
    }
    __syncthreads();
    if (tid == 0) {
        __threadfence();
        atomicAdd(&g_cnt[layer][gy], 1);
        while (*((volatile int*)&g_cnt[layer][gy]) < 4) __nanosleep(64);
    }
    __syncthreads();

    // ---------------- mainloop (R8/R13) --------------------------------------
    float acc[2][8][4];
#pragma unroll
    for (int i = 0; i < 2; i++)
#pragma unroll
        for (int j = 0; j < 8; j++)
#pragma unroll
            for (int q = 0; q < 4; q++) acc[i][j][q] = 0.0f;

    const __nv_bfloat16* whb = Whi + (size_t)n0 * KDIM;
    const __nv_bfloat16* wlb = Wlo + (size_t)n0 * KDIM;

    auto load_stage = [&](int it) {
        int buf = it % STAGES;
        __nv_bfloat16* st = smem + buf * STAGE_ELEMS;
        int kb = it * BK;
#pragma unroll
        for (int i = 0; i < 2; i++) {
            int idx = tid * 2 + i;          // 0..511
            int row = idx >> 2;
            int c   = (idx & 3) * 8;
            int so  = swoff(row, c);
            size_t ga = (size_t)(m0 + row) * KDIM + kb + c;
            size_t gw = (size_t)row * KDIM + kb + c;
            cp16(st + so,                  Ahi + ga);
            cp16(st + SLOT_ELEMS + so,     Alo + ga);
            cp16(st + 2 * SLOT_ELEMS + so, whb + gw);
            cp16(st + 3 * SLOT_ELEMS + so, wlb + gw);
        }
    };

    load_stage(0); CP_COMMIT();
    load_stage(1); CP_COMMIT();

    for (int it = 0; it < 8; ++it) {
        if (it == 7) asm volatile("cp.async.wait_group 0;\n" ::: "memory");
        else         asm volatile("cp.async.wait_group 1;\n" ::: "memory");
        __syncthreads();
        if (it + 2 < 8) load_stage(it + 2);
        CP_COMMIT();

        const __nv_bfloat16* st = smem + (it % STAGES) * STAGE_ELEMS;
#pragma unroll
        for (int ks = 0; ks < 2; ++ks) {
            int k0 = ks * 16;
            int ra = wm * 32 + (lane & 15);
            int ca = k0 + ((lane & 16) ? 8 : 0);
            int rb = wn * 64 + ((lane & 16) ? 8 : 0) + (lane & 7);
            int cb = k0 + ((lane & 8) ? 8 : 0);

            uint32_t afh[2][4], afl[2][4];
#pragma unroll
            for (int mi = 0; mi < 2; mi++) {
                int so = swoff(ra + mi * 16, ca);
                ldsm_x4(afh[mi], st + so);
                ldsm_x4(afl[mi], st + SLOT_ELEMS + so);
            }
            uint32_t bqh[4][4];
#pragma unroll
            for (int nj = 0; nj < 4; nj++)
                ldsm_x4(bqh[nj], st + 2 * SLOT_ELEMS + swoff(rb + nj * 16, cb));
            // product 1: Ahi * Whi
#pragma unroll
            for (int mi = 0; mi < 2; mi++)
#pragma unroll
                for (int ni = 0; ni < 8; ni++)
                    mma16816(acc[mi][ni], afh[mi], bqh[ni >> 1][(ni & 1) * 2],
                             bqh[ni >> 1][(ni & 1) * 2 + 1]);
            // product 3: Alo * Whi  (bqh dead afterwards)
#pragma unroll
            for (int mi = 0; mi < 2; mi++)
#pragma unroll
                for (int ni = 0; ni < 8; ni++)
                    mma16816(acc[mi][ni], afl[mi], bqh[ni >> 1][(ni & 1) * 2],
                             bqh[ni >> 1][(ni & 1) * 2 + 1]);
            // product 2: Ahi * Wlo
            uint32_t bql[4][4];
#pragma unroll
            for (int nj = 0; nj < 4; nj++)
                ldsm_x4(bql[nj], st + 3 * SLOT_ELEMS + swoff(rb + nj * 16, cb));
#pragma unroll
            for (int mi = 0; mi < 2; mi++)
#pragma unroll
                for (int ni = 0; ni < 8; ni++)
                    mma16816(acc[mi][ni], afh[mi], bql[ni >> 1][(ni & 1) * 2],
                             bql[ni >> 1][(ni & 1) * 2 + 1]);
        }
    }

    // ---------------- epilogue: (a,v) -> in-chunk prefix (P,Q) ----------------
    __syncthreads();            // mainloop fully done; smem now reusable
    float2* av_sm  = reinterpret_cast<float2*>(smem);            // [128][64] 64KB
    float2* red_sm = reinterpret_cast<float2*>(smem) + 128 * 64; // [4][64]  2KB

    // phase 1: fragments -> (a,v) staged in SMEM
    const int tig = lane & 3;
    const int grp = lane >> 2;
#pragma unroll
    for (int mi = 0; mi < 2; mi++) {
        int s0 = wm * 32 + mi * 16 + grp;              // local row 0..127
#pragma unroll
        for (int ni = 0; ni < 8; ni++) {
            int col = n0 + wn * 64 + ni * 8 + tig * 2; // global interleaved col
            int chl = wn * 32 + ni * 4 + tig;          // local channel 0..63
            float bg = bc[col];
            float bh = bc[col + 1];
            av_sm[s0 * 64 + chl] =
                av_from(acc[mi][ni][0] + bg, acc[mi][ni][1] + bh);
            av_sm[(s0 + 8) * 64 + chl] =
                av_from(acc[mi][ni][2] + bg, acc[mi][ni][3] + bh);
        }
    }
    __syncthreads();

    const int g = tid >> 6;          // group 0..3 (32 rows each)
    const int d = tid & 63;          // local channel
    // phase 2: local prefix scan within group, stored in-place
    {
        float A = 1.0f, V = 0.0f;
#pragma unroll 8
        for (int s = g * 32; s < g * 32 + 32; s++) {
            float2 t = av_sm[s * 64 + d];
            V = fmaf(t.x, V, t.y);
            A *= t.x;
            av_sm[s * 64 + d] = make_float2(A, V);
        }
        red_sm[g * 64 + d] = make_float2(A, V);
    }
    __syncthreads();
    // phase 3: apply group-prefix offset; write (P,Q) + chunk aggregate
    {
        float Ap = 1.0f, Vp = 0.0f;
#pragma unroll
        for (int q = 0; q < 3; q++) {
            if (q < g) {
                float2 t = red_sm[q * 64 + d];
                Vp = fmaf(t.x, Vp, t.y);
                Ap *= t.x;
            }
        }
        const int dg = (n0 >> 1) + d;          // global channel
        float P = 1.0f, Q = 0.0f;
#pragma unroll 8
        for (int s = g * 32; s < g * 32 + 32; s++) {
            float2 t = av_sm[s * 64 + d];
            P = t.x * Ap;
            Q = fmaf(t.x, Vp, t.y);
            g_av[(size_t)(m0 + s) * 256 + dg] = make_float2(P, Q);
        }
        if (g == 3) {
            const int b  = m0 >> 13;
            const int ck = (m0 >> 7) & 63;
            g_agg[(b * NCH + ck) * 256 + dg] = make_float2(P, Q);
        }
    }
}

// -------------------- chunked scan -----------------------------------------
// combine: sequential over NCH chunk aggregates -> per-chunk starting h0.
// Also resets this layer's prologue counters for the next graph replay.
__global__ void scan_combine(int layer) {
    int b = blockIdx.x, d = threadIdx.x;
    int t = b * 256 + d;
    if (t < 512) g_cnt[layer][t] = 0;
    float h = 0.5f;
    for (int c0 = 0; c0 < NCH; c0 += 8) {
        float2 t2[8];
#pragma unroll
        for (int j = 0; j < 8; j++)
            t2[j] = g_agg[(b * NCH + c0 + j) * 256 + d];
#pragma unroll
        for (int j = 0; j < 8; j++) {
            g_h0[(b * NCH + c0 + j) * 256 + d] = h;
            h = fmaf(t2[j].x, h, t2[j].y);
        }
    }
}

// pass3 layer 1 (elementwise): write out1 fp32; last row -> h[1] tail
__global__ void scan_pass3_l1(float* __restrict__ dout) {
    int b = blockIdx.x, ch = blockIdx.y, d = threadIdx.x;
    float h0v = g_h0[(b * NCH + ch) * 256 + d];
    size_t row0 = (size_t)b * SEQ + ch * CHLEN;
    float hlast = 0.0f;
#pragma unroll 8
    for (int s = 0; s < CHLEN; s++) {
        size_t idx = (row0 + s) * 256 + d;
        float2 t = g_av[idx];
        float h = fmaf(t.x, h0v, t.y);
        dout[idx] = h;
        if (s == CHLEN - 1) hlast = h;
    }
    if (ch == NCH - 1) dout[OUT1_ELEMS + 2048 + b * 256 + d] = hlast;
}

// -------------------- launch -----------------------------------------------
extern "C" void kernel_launch(void* const* d_in, const int* in_sizes, int n_in,
                              void* d_out, int out_size) {
    const float* x  = (const float*)d_in[0];
    const float* W0 = (const float*)d_in[1];
    const float* b0 = (const float*)d_in[2];
    const float* W1 = (const float*)d_in[3];
    const float* b1 = (const float*)d_in[4];
    float* out = (float*)d_out;

    cudaFuncSetAttribute(gemm_kernel,
                         cudaFuncAttributeMaxDynamicSharedMemorySize, SMEM_BYTES);

    convert_wb_kernel<<<1028, 256>>>(W0, W1, b0, b1);

    dim3 ggrid(4, 512);        // x = N blocks (fast) so A-panel reuse hits L2
    dim3 sgrid(BATCH, NCH);

    gemm_kernel<<<ggrid, 256, SMEM_BYTES>>>(0, x, out);  // x-split prologue + pass1
    scan_combine<<<BATCH, 256>>>(0);
    gemm_kernel<<<ggrid, 256, SMEM_BYTES>>>(1, x, out);  // pass3_l0 prologue + pass1
    scan_combine<<<BATCH, 256>>>(1);
    scan_pass3_l1<<<sgrid, 256>>>(out);
}

// round 16
// speedup vs baseline: 1.0794x; 1.0794x over previous
#include <cuda_runtime.h>
#include <cuda_bf16.h>
#include <cstdint>
#include <cstddef>

// ---------------------------------------------------------------------------
// MinGRU (2 layers), B=8, S=8192, DIN=DH=256.
//   gh = x @ W^T + b; a = sigmoid(-gate); v = sigmoid(gate)*g(hidden)
//   h_t = a_t*h_{t-1} + v_t, h0 = 0.5  (linear-space equivalent of reference)
// fp32 GEMM emulated with 3 bf16 mma.sync products: Ahi*Whi + Ahi*Wlo + Alo*Whi.
// R15: R13 data flow unchanged. scan_combine inlined into the gemm via a
//      last-CTA-done atomic (no spin, deterministic, replay-safe counter);
//      convert_x + convert_wb merged into one launch. 7 -> 5 launches.
// ---------------------------------------------------------------------------

#define M_ROWS   65536
#define KDIM     256
#define BATCH    8
#define SEQ      8192
#define NCH      64
#define CHLEN    128
#define OUT1_ELEMS 16777216

#define STAGES     3
#define BK         32
#define SLOT_ELEMS (128 * 32)                // 4096 elems = 8192 B (no padding)
#define STAGE_ELEMS (4 * SLOT_ELEMS)         // Ahi, Alo, Whi, Wlo
#define SMEM_BYTES (STAGES * STAGE_ELEMS * 2)   // 98304

// swizzled element offset within a slot; col is bf16 elem 0..31, col%8==0 use
__device__ __forceinline__ int swoff(int row, int col) {
    return row * 32 + ((((col >> 3) ^ ((row >> 1) & 3)) << 3) | (col & 7));
}

// -------------------- scratch (device globals; no allocation) --------------
__device__ __nv_bfloat16 g_xhi[16777216];     // 32 MB  (A hi; x-split then h-split)
__device__ __nv_bfloat16 g_xlo[16777216];     // 32 MB  (A lo)
__device__ float2        g_av [16777216];     // 128 MB per-row chunk prefix (P,Q)
__device__ __nv_bfloat16 g_whi[2][131072];    // W hi, interleaved rows
__device__ __nv_bfloat16 g_wlo[2][131072];    // W lo
__device__ float         g_bc [2][512];       // bias, interleaved
__device__ float2        g_agg[BATCH * NCH * 256];
__device__ float         g_h0 [BATCH * NCH * 256];
__device__ int           g_done[2];           // gemm arrival counters (self-reset)

// -------------------- small helpers ----------------------------------------
__device__ __forceinline__ void cp16(void* dst, const void* src) {
    uint32_t d = (uint32_t)__cvta_generic_to_shared(dst);
    asm volatile("cp.async.cg.shared.global [%0], [%1], 16;\n" :: "r"(d), "l"(src));
}
#define CP_COMMIT() asm volatile("cp.async.commit_group;\n" ::: "memory")

__device__ __forceinline__ void ldsm_x4(uint32_t (&r)[4], const void* p) {
    uint32_t a = (uint32_t)__cvta_generic_to_shared(p);
    asm volatile("ldmatrix.sync.aligned.m8n8.x4.shared.b16 {%0,%1,%2,%3}, [%4];"
                 : "=r"(r[0]), "=r"(r[1]), "=r"(r[2]), "=r"(r[3]) : "r"(a));
}

__device__ __forceinline__ void mma16816(float* c, const uint32_t* a, uint32_t b0, uint32_t b1) {
    asm volatile(
        "mma.sync.aligned.m16n8k16.row.col.f32.bf16.bf16.f32 "
        "{%0,%1,%2,%3}, {%4,%5,%6,%7}, {%8,%9}, {%0,%1,%2,%3};"
        : "+f"(c[0]), "+f"(c[1]), "+f"(c[2]), "+f"(c[3])
        : "r"(a[0]), "r"(a[1]), "r"(a[2]), "r"(a[3]), "r"(b0), "r"(b1));
}

// a = sigmoid(-gate), v = sigmoid(gate)*g(hidden)
__device__ __forceinline__ float2 av_from(float gate, float hid) {
    float e   = __expf(-fabsf(gate));
    float inv = 1.0f / (1.0f + e);
    float z, a;
    if (gate >= 0.0f) { z = inv;     a = e * inv; }
    else              { z = e * inv; a = inv;     }
    float g = (hid >= 0.0f) ? (hid + 0.5f) : (1.0f / (1.0f + __expf(-hid)));
    return make_float2(a, z * g);
}

// -------------------- fused input conversion (one launch) -------------------
// blocks [0,16384): x fp32 -> hi/lo bf16 split (4 elems per thread)
// blocks [16384,17412): W rows interleaved (gate_d, hidden_d) + bias
__global__ void convert_inputs(const float* __restrict__ x,
                               const float* __restrict__ W0, const float* __restrict__ W1,
                               const float* __restrict__ b0, const float* __restrict__ b1) {
    int bid = blockIdx.x;
    if (bid < 16384) {
        size_t i = (size_t)bid * blockDim.x + threadIdx.x;
        float4 v = reinterpret_cast<const float4*>(x)[i];
        float vv[4] = {v.x, v.y, v.z, v.w};
        ushort4 hi, lo;
        unsigned short* hp = &hi.x;
        unsigned short* lp = &lo.x;
#pragma unroll
        for (int j = 0; j < 4; j++) {
            __nv_bfloat16 h = __float2bfloat16(vv[j]);
            float r = vv[j] - __bfloat162float(h);
            hp[j] = __bfloat16_as_ushort(h);
            lp[j] = __bfloat16_as_ushort(__float2bfloat16(r));
        }
        reinterpret_cast<ushort4*>(g_xhi)[i] = hi;
        reinterpret_cast<ushort4*>(g_xlo)[i] = lo;
    } else {
        int idx = (bid - 16384) * blockDim.x + threadIdx.x;  // 0..263167
        if (idx < 262144) {
            int l = idx >> 17;
            int r = (idx >> 8) & 511;
            int k = idx & 255;
            const float* W = l ? W1 : W0;
            int src = (r & 1) ? (256 + (r >> 1)) : (r >> 1);
            float w = W[src * 256 + k];
            __nv_bfloat16 h = __float2bfloat16(w);
            g_whi[l][r * 256 + k] = h;
            g_wlo[l][r * 256 + k] = __float2bfloat16(w - __bfloat162float(h));
        } else {
            int j = idx - 262144;                 // 0..1023
            int l = j >> 9, n = j & 511;
            int src = (n & 1) ? (256 + (n >> 1)) : (n >> 1);
            g_bc[l][n] = (l ? b1 : b0)[src];
        }
    }
}

// -------------------- GEMM + prefix epilogue + inline combine ----------------
// Block tile 128x128 (one scan chunk x 64 channels). 8 iterations; stage c
// holds {Ahi,Alo,Whi,Wlo} for k-chunk c (swizzled); all 3 products per chunk.
// Epilogue: (a,v) -> SMEM; per-row in-chunk prefix (P,Q) to g_av; chunk
// aggregate to g_agg. The LAST CTA (atomic counter) then runs the cross-chunk
// combine (g_agg -> g_h0) inline and resets the counter for the next replay.
__global__ void __launch_bounds__(256, 2) gemm_kernel(int layer) {
    const __nv_bfloat16* __restrict__ Ahi = g_xhi;
    const __nv_bfloat16* __restrict__ Alo = g_xlo;
    const __nv_bfloat16* __restrict__ Whi = g_whi[layer];
    const __nv_bfloat16* __restrict__ Wlo = g_wlo[layer];
    const float* __restrict__ bc = g_bc[layer];

    extern __shared__ __align__(128) __nv_bfloat16 smem[];

    const int tid  = threadIdx.x;
    const int lane = tid & 31;
    const int warp = tid >> 5;
    const int wm   = warp & 3;   // 4 warps along M (32 rows each)
    const int wn   = warp >> 2;  // 2 warps along N (64 cols each)
    const int m0   = blockIdx.y * 128;
    const int n0   = blockIdx.x * 128;

    float acc[2][8][4];
#pragma unroll
    for (int i = 0; i < 2; i++)
#pragma unroll
        for (int j = 0; j < 8; j++)
#pragma unroll
            for (int q = 0; q < 4; q++) acc[i][j][q] = 0.0f;

    const __nv_bfloat16* whb = Whi + (size_t)n0 * KDIM;
    const __nv_bfloat16* wlb = Wlo + (size_t)n0 * KDIM;

    auto load_stage = [&](int it) {
        int buf = it % STAGES;
        __nv_bfloat16* st = smem + buf * STAGE_ELEMS;
        int kb = it * BK;
#pragma unroll
        for (int i = 0; i < 2; i++) {
            int idx = tid * 2 + i;          // 0..511
            int row = idx >> 2;
            int c   = (idx & 3) * 8;
            int so  = swoff(row, c);
            size_t ga = (size_t)(m0 + row) * KDIM + kb + c;
            size_t gw = (size_t)row * KDIM + kb + c;
            cp16(st + so,                  Ahi + ga);
            cp16(st + SLOT_ELEMS + so,     Alo + ga);
            cp16(st + 2 * SLOT_ELEMS + so, whb + gw);
            cp16(st + 3 * SLOT_ELEMS + so, wlb + gw);
        }
    };

    load_stage(0); CP_COMMIT();
    load_stage(1); CP_COMMIT();

    for (int it = 0; it < 8; ++it) {
        if (it == 7) asm volatile("cp.async.wait_group 0;\n" ::: "memory");
        else         asm volatile("cp.async.wait_group 1;\n" ::: "memory");
        __syncthreads();
        if (it + 2 < 8) load_stage(it + 2);
        CP_COMMIT();

        const __nv_bfloat16* st = smem + (it % STAGES) * STAGE_ELEMS;
#pragma unroll
        for (int ks = 0; ks < 2; ++ks) {
            int k0 = ks * 16;
            int ra = wm * 32 + (lane & 15);
            int ca = k0 + ((lane & 16) ? 8 : 0);
            int rb = wn * 64 + ((lane & 16) ? 8 : 0) + (lane & 7);
            int cb = k0 + ((lane & 8) ? 8 : 0);

            uint32_t afh[2][4], afl[2][4];
#pragma unroll
            for (int mi = 0; mi < 2; mi++) {
                int so = swoff(ra + mi * 16, ca);
                ldsm_x4(afh[mi], st + so);
                ldsm_x4(afl[mi], st + SLOT_ELEMS + so);
            }
            uint32_t bqh[4][4];
#pragma unroll
            for (int nj = 0; nj < 4; nj++)
                ldsm_x4(bqh[nj], st + 2 * SLOT_ELEMS + swoff(rb + nj * 16, cb));
            // product 1: Ahi * Whi
#pragma unroll
            for (int mi = 0; mi < 2; mi++)
#pragma unroll
                for (int ni = 0; ni < 8; ni++)
                    mma16816(acc[mi][ni], afh[mi], bqh[ni >> 1][(ni & 1) * 2],
                             bqh[ni >> 1][(ni & 1) * 2 + 1]);
            // product 3: Alo * Whi  (bqh dead afterwards)
#pragma unroll
            for (int mi = 0; mi < 2; mi++)
#pragma unroll
                for (int ni = 0; ni < 8; ni++)
                    mma16816(acc[mi][ni], afl[mi], bqh[ni >> 1][(ni & 1) * 2],
                             bqh[ni >> 1][(ni & 1) * 2 + 1]);
            // product 2: Ahi * Wlo
            uint32_t bql[4][4];
#pragma unroll
            for (int nj = 0; nj < 4; nj++)
                ldsm_x4(bql[nj], st + 3 * SLOT_ELEMS + swoff(rb + nj * 16, cb));
#pragma unroll
            for (int mi = 0; mi < 2; mi++)
#pragma unroll
                for (int ni = 0; ni < 8; ni++)
                    mma16816(acc[mi][ni], afh[mi], bql[ni >> 1][(ni & 1) * 2],
                             bql[ni >> 1][(ni & 1) * 2 + 1]);
        }
    }

    // ---------------- epilogue: (a,v) -> in-chunk prefix (P,Q) ----------------
    __syncthreads();            // mainloop fully done; smem now reusable
    float2* av_sm  = reinterpret_cast<float2*>(smem);            // [128][64] 64KB
    float2* red_sm = reinterpret_cast<float2*>(smem) + 128 * 64; // [4][64]  2KB

    // phase 1: fragments -> (a,v) staged in SMEM
    const int tig = lane & 3;
    const int grp = lane >> 2;
#pragma unroll
    for (int mi = 0; mi < 2; mi++) {
        int s0 = wm * 32 + mi * 16 + grp;              // local row 0..127
#pragma unroll
        for (int ni = 0; ni < 8; ni++) {
            int col = n0 + wn * 64 + ni * 8 + tig * 2; // global interleaved col
            int chl = wn * 32 + ni * 4 + tig;          // local channel 0..63
            float bg = bc[col];
            float bh = bc[col + 1];
            av_sm[s0 * 64 + chl] =
                av_from(acc[mi][ni][0] + bg, acc[mi][ni][1] + bh);
            av_sm[(s0 + 8) * 64 + chl] =
                av_from(acc[mi][ni][2] + bg, acc[mi][ni][3] + bh);
        }
    }
    __syncthreads();

    const int g = tid >> 6;          // group 0..3 (32 rows each)
    const int d = tid & 63;          // local channel
    // phase 2: local prefix scan within group, stored in-place
    {
        float A = 1.0f, V = 0.0f;
#pragma unroll 8
        for (int s = g * 32; s < g * 32 + 32; s++) {
            float2 t = av_sm[s * 64 + d];
            V = fmaf(t.x, V, t.y);
            A *= t.x;
            av_sm[s * 64 + d] = make_float2(A, V);
        }
        red_sm[g * 64 + d] = make_float2(A, V);
    }
    __syncthreads();
    // phase 3: apply group-prefix offset; write (P,Q) + chunk aggregate
    {
        float Ap = 1.0f, Vp = 0.0f;
#pragma unroll
        for (int q = 0; q < 3; q++) {
            if (q < g) {
                float2 t = red_sm[q * 64 + d];
                Vp = fmaf(t.x, Vp, t.y);
                Ap *= t.x;
            }
        }
        const int dg = (n0 >> 1) + d;          // global channel
        float P = 1.0f, Q = 0.0f;
#pragma unroll 8
        for (int s = g * 32; s < g * 32 + 32; s++) {
            float2 t = av_sm[s * 64 + d];
            P = t.x * Ap;
            Q = fmaf(t.x, Vp, t.y);
            g_av[(size_t)(m0 + s) * 256 + dg] = make_float2(P, Q);
        }
        if (g == 3) {
            const int b  = m0 >> 13;
            const int ck = (m0 >> 7) & 63;
            g_agg[(b * NCH + ck) * 256 + dg] = make_float2(P, Q);
        }
    }

    // ---------------- last-CTA inline combine (replaces scan_combine) --------
    __shared__ int is_last;
    __syncthreads();
    if (tid == 0) {
        __threadfence();                                 // release g_agg writes
        int old = atomicAdd(&g_done[layer], 1);
        is_last = (old == 2048 - 1);
    }
    __syncthreads();
    if (is_last) {
        if (tid == 0) { g_done[layer] = 0; }             // reset for next replay
        __threadfence();                                 // acquire g_agg
        // 2048 channels, 8 per thread; 4-step load batching (32 loads in flight)
        float h[8];
#pragma unroll
        for (int j = 0; j < 8; j++) h[j] = 0.5f;
        for (int c0 = 0; c0 < NCH; c0 += 4) {
            float2 t2[8][4];
#pragma unroll
            for (int j = 0; j < 8; j++) {
                int ch = tid + j * 256;
                int b = ch >> 8, dd = ch & 255;
#pragma unroll
                for (int k = 0; k < 4; k++)
                    t2[j][k] = g_agg[(b * NCH + c0 + k) * 256 + dd];
            }
#pragma unroll
            for (int j = 0; j < 8; j++) {
                int ch = tid + j * 256;
                int b = ch >> 8, dd = ch & 255;
#pragma unroll
                for (int k = 0; k < 4; k++) {
                    g_h0[(b * NCH + c0 + k) * 256 + dd] = h[j];
                    h[j] = fmaf(t2[j][k].x, h[j], t2[j][k].y);
                }
            }
        }
    }
}

// pass3 layer 0 (elementwise): h = P*h0 + Q; write out0 as bf16 hi/lo split;
// last row -> h[0] tail of d_out
__global__ void scan_pass3_l0(float* __restrict__ dout) {
    int b = blockIdx.x, ch = blockIdx.y, d = threadIdx.x;
    float h0v = g_h0[(b * NCH + ch) * 256 + d];
    size_t row0 = (size_t)b * SEQ + ch * CHLEN;
    float hlast = 0.0f;
#pragma unroll 8
    for (int s = 0; s < CHLEN; s++) {
        size_t idx = (row0 + s) * 256 + d;
        float2 t = g_av[idx];
        float h = fmaf(t.x, h0v, t.y);
        __nv_bfloat16 hi = __float2bfloat16(h);
        g_xhi[idx] = hi;
        g_xlo[idx] = __float2bfloat16(h - __bfloat162float(hi));
        if (s == CHLEN - 1) hlast = h;
    }
    if (ch == NCH - 1) dout[OUT1_ELEMS + b * 256 + d] = hlast;
}

// pass3 layer 1 (elementwise): write out1 fp32; last row -> h[1] tail
__global__ void scan_pass3_l1(float* __restrict__ dout) {
    int b = blockIdx.x, ch = blockIdx.y, d = threadIdx.x;
    float h0v = g_h0[(b * NCH + ch) * 256 + d];
    size_t row0 = (size_t)b * SEQ + ch * CHLEN;
    float hlast = 0.0f;
#pragma unroll 8
    for (int s = 0; s < CHLEN; s++) {
        size_t idx = (row0 + s) * 256 + d;
        float2 t = g_av[idx];
        float h = fmaf(t.x, h0v, t.y);
        dout[idx] = h;
        if (s == CHLEN - 1) hlast = h;
    }
    if (ch == NCH - 1) dout[OUT1_ELEMS + 2048 + b * 256 + d] = hlast;
}

// -------------------- launch -----------------------------------------------
extern "C" void kernel_launch(void* const* d_in, const int* in_sizes, int n_in,
                              void* d_out, int out_size) {
    const float* x  = (const float*)d_in[0];
    const float* W0 = (const float*)d_in[1];
    const float* b0 = (const float*)d_in[2];
    const float* W1 = (const float*)d_in[3];
    const float* b1 = (const float*)d_in[4];
    float* out = (float*)d_out;

    cudaFuncSetAttribute(gemm_kernel,
                         cudaFuncAttributeMaxDynamicSharedMemorySize, SMEM_BYTES);

    dim3 ggrid(4, 512);        // x = N blocks (fast) so A-panel reuse hits L2
    dim3 sgrid(BATCH, NCH);

    convert_inputs<<<17412, 256>>>(x, W0, W1, b0, b1);

    gemm_kernel<<<ggrid, 256, SMEM_BYTES>>>(0);   // + prefix pass1 + inline combine
    scan_pass3_l0<<<sgrid, 256>>>(out);

    gemm_kernel<<<ggrid, 256, SMEM_BYTES>>>(1);   // + prefix pass1 + inline combine
    scan_pass3_l1<<<sgrid, 256>>>(out);
}

// round 17
// speedup vs baseline: 1.1495x; 1.0649x over previous
#include <cuda_runtime.h>
#include <cuda_bf16.h>
#include <cstdint>
#include <cstddef>

// ---------------------------------------------------------------------------
// MinGRU (2 layers), B=8, S=8192, DIN=DH=256.
//   gh = x @ W^T + b; a = sigmoid(-gate); v = sigmoid(gate)*g(hidden)
//   h_t = a_t*h_{t-1} + v_t, h0 = 0.5  (linear-space equivalent of reference)
// fp32 GEMM emulated with 3 bf16 mma.sync products: Ahi*Whi + Ahi*Wlo + Alo*Whi.
// R16: R13 structure verbatim (best verified: gemm + (P,Q) prefix epilogue,
//      separate 8-CTA scan_combine, elementwise pass3) + merged convert launch
//      (the only safe keeper from R15). Inline-combine and all prologue
//      fusions reverted — three rounds showed cross-CTA coupling in the GEMM
//      always loses to a small separate launch.
// ---------------------------------------------------------------------------

#define M_ROWS   65536
#define KDIM     256
#define BATCH    8
#define SEQ      8192
#define NCH      64
#define CHLEN    128
#define OUT1_ELEMS 16777216

#define STAGES     3
#define BK         32
#define SLOT_ELEMS (128 * 32)                // 4096 elems = 8192 B (no padding)
#define STAGE_ELEMS (4 * SLOT_ELEMS)         // Ahi, Alo, Whi, Wlo
#define SMEM_BYTES (STAGES * STAGE_ELEMS * 2)   // 98304

// swizzled element offset within a slot; col is bf16 elem 0..31, col%8==0 use
__device__ __forceinline__ int swoff(int row, int col) {
    return row * 32 + ((((col >> 3) ^ ((row >> 1) & 3)) << 3) | (col & 7));
}

// -------------------- scratch (device globals; no allocation) --------------
__device__ __nv_bfloat16 g_xhi[16777216];     // 32 MB  (A hi; x-split then h-split)
__device__ __nv_bfloat16 g_xlo[16777216];     // 32 MB  (A lo)
__device__ float2        g_av [16777216];     // 128 MB per-row chunk prefix (P,Q)
__device__ __nv_bfloat16 g_whi[2][131072];    // W hi, interleaved rows
__device__ __nv_bfloat16 g_wlo[2][131072];    // W lo
__device__ float         g_bc [2][512];       // bias, interleaved
__device__ float2        g_agg[BATCH * NCH * 256];
__device__ float         g_h0 [BATCH * NCH * 256];

// -------------------- small helpers ----------------------------------------
__device__ __forceinline__ void cp16(void* dst, const void* src) {
    uint32_t d = (uint32_t)__cvta_generic_to_shared(dst);
    asm volatile("cp.async.cg.shared.global [%0], [%1], 16;\n" :: "r"(d), "l"(src));
}
#define CP_COMMIT() asm volatile("cp.async.commit_group;\n" ::: "memory")

__device__ __forceinline__ void ldsm_x4(uint32_t (&r)[4], const void* p) {
    uint32_t a = (uint32_t)__cvta_generic_to_shared(p);
    asm volatile("ldmatrix.sync.aligned.m8n8.x4.shared.b16 {%0,%1,%2,%3}, [%4];"
                 : "=r"(r[0]), "=r"(r[1]), "=r"(r[2]), "=r"(r[3]) : "r"(a));
}

__device__ __forceinline__ void mma16816(float* c, const uint32_t* a, uint32_t b0, uint32_t b1) {
    asm volatile(
        "mma.sync.aligned.m16n8k16.row.col.f32.bf16.bf16.f32 "
        "{%0,%1,%2,%3}, {%4,%5,%6,%7}, {%8,%9}, {%0,%1,%2,%3};"
        : "+f"(c[0]), "+f"(c[1]), "+f"(c[2]), "+f"(c[3])
        : "r"(a[0]), "r"(a[1]), "r"(a[2]), "r"(a[3]), "r"(b0), "r"(b1));
}

// a = sigmoid(-gate), v = sigmoid(gate)*g(hidden)
__device__ __forceinline__ float2 av_from(float gate, float hid) {
    float e   = __expf(-fabsf(gate));
    float inv = 1.0f / (1.0f + e);
    float z, a;
    if (gate >= 0.0f) { z = inv;     a = e * inv; }
    else              { z = e * inv; a = inv;     }
    float g = (hid >= 0.0f) ? (hid + 0.5f) : (1.0f / (1.0f + __expf(-hid)));
    return make_float2(a, z * g);
}

// -------------------- fused input conversion (one launch) -------------------
// blocks [0,16384): x fp32 -> hi/lo bf16 split (4 elems per thread)
// blocks [16384,17412): W rows interleaved (gate_d, hidden_d) + bias
__global__ void convert_inputs(const float* __restrict__ x,
                               const float* __restrict__ W0, const float* __restrict__ W1,
                               const float* __restrict__ b0, const float* __restrict__ b1) {
    int bid = blockIdx.x;
    if (bid < 16384) {
        size_t i = (size_t)bid * blockDim.x + threadIdx.x;
        float4 v = reinterpret_cast<const float4*>(x)[i];
        float vv[4] = {v.x, v.y, v.z, v.w};
        ushort4 hi, lo;
        unsigned short* hp = &hi.x;
        unsigned short* lp = &lo.x;
#pragma unroll
        for (int j = 0; j < 4; j++) {
            __nv_bfloat16 h = __float2bfloat16(vv[j]);
            float r = vv[j] - __bfloat162float(h);
            hp[j] = __bfloat16_as_ushort(h);
            lp[j] = __bfloat16_as_ushort(__float2bfloat16(r));
        }
        reinterpret_cast<ushort4*>(g_xhi)[i] = hi;
        reinterpret_cast<ushort4*>(g_xlo)[i] = lo;
    } else {
        int idx = (bid - 16384) * blockDim.x + threadIdx.x;  // 0..263167
        if (idx < 262144) {
            int l = idx >> 17;
            int r = (idx >> 8) & 511;
            int k = idx & 255;
            const float* W = l ? W1 : W0;
            int src = (r & 1) ? (256 + (r >> 1)) : (r >> 1);
            float w = W[src * 256 + k];
            __nv_bfloat16 h = __float2bfloat16(w);
            g_whi[l][r * 256 + k] = h;
            g_wlo[l][r * 256 + k] = __float2bfloat16(w - __bfloat162float(h));
        } else {
            int j = idx - 262144;                 // 0..1023
            int l = j >> 9, n = j & 511;
            int src = (n & 1) ? (256 + (n >> 1)) : (n >> 1);
            g_bc[l][n] = (l ? b1 : b0)[src];
        }
    }
}

// -------------------- GEMM + epilogue with in-chunk prefix ------------------
// Block tile 128x128 (one scan chunk x 64 channels). 8 iterations; stage c
// holds {Ahi,Alo,Whi,Wlo} for k-chunk c (swizzled); all 3 products per chunk.
// Epilogue: (a,v) -> SMEM; 4x32-row local prefix scans in-place; group-offset
// combine; write per-row (P,Q) to g_av and chunk aggregate to g_agg.
__global__ void __launch_bounds__(256, 2) gemm_kernel(int layer) {
    const __nv_bfloat16* __restrict__ Ahi = g_xhi;
    const __nv_bfloat16* __restrict__ Alo = g_xlo;
    const __nv_bfloat16* __restrict__ Whi = g_whi[layer];
    const __nv_bfloat16* __restrict__ Wlo = g_wlo[layer];
    const float* __restrict__ bc = g_bc[layer];

    extern __shared__ __align__(128) __nv_bfloat16 smem[];

    const int tid  = threadIdx.x;
    const int lane = tid & 31;
    const int warp = tid >> 5;
    const int wm   = warp & 3;   // 4 warps along M (32 rows each)
    const int wn   = warp >> 2;  // 2 warps along N (64 cols each)
    const int m0   = blockIdx.y * 128;
    const int n0   = blockIdx.x * 128;

    float acc[2][8][4];
#pragma unroll
    for (int i = 0; i < 2; i++)
#pragma unroll
        for (int j = 0; j < 8; j++)
#pragma unroll
            for (int q = 0; q < 4; q++) acc[i][j][q] = 0.0f;

    const __nv_bfloat16* whb = Whi + (size_t)n0 * KDIM;
    const __nv_bfloat16* wlb = Wlo + (size_t)n0 * KDIM;

    auto load_stage = [&](int it) {
        int buf = it % STAGES;
        __nv_bfloat16* st = smem + buf * STAGE_ELEMS;
        int kb = it * BK;
#pragma unroll
        for (int i = 0; i < 2; i++) {
            int idx = tid * 2 + i;          // 0..511
            int row = idx >> 2;
            int c   = (idx & 3) * 8;
            int so  = swoff(row, c);
            size_t ga = (size_t)(m0 + row) * KDIM + kb + c;
            size_t gw = (size_t)row * KDIM + kb + c;
            cp16(st + so,                  Ahi + ga);
            cp16(st + SLOT_ELEMS + so,     Alo + ga);
            cp16(st + 2 * SLOT_ELEMS + so, whb + gw);
            cp16(st + 3 * SLOT_ELEMS + so, wlb + gw);
        }
    };

    load_stage(0); CP_COMMIT();
    load_stage(1); CP_COMMIT();

    for (int it = 0; it < 8; ++it) {
        if (it == 7) asm volatile("cp.async.wait_group 0;\n" ::: "memory");
        else         asm volatile("cp.async.wait_group 1;\n" ::: "memory");
        __syncthreads();
        if (it + 2 < 8) load_stage(it + 2);
        CP_COMMIT();

        const __nv_bfloat16* st = smem + (it % STAGES) * STAGE_ELEMS;
#pragma unroll
        for (int ks = 0; ks < 2; ++ks) {
            int k0 = ks * 16;
            int ra = wm * 32 + (lane & 15);
            int ca = k0 + ((lane & 16) ? 8 : 0);
            int rb = wn * 64 + ((lane & 16) ? 8 : 0) + (lane & 7);
            int cb = k0 + ((lane & 8) ? 8 : 0);

            uint32_t afh[2][4], afl[2][4];
#pragma unroll
            for (int mi = 0; mi < 2; mi++) {
                int so = swoff(ra + mi * 16, ca);
                ldsm_x4(afh[mi], st + so);
                ldsm_x4(afl[mi], st + SLOT_ELEMS + so);
            }
            uint32_t bqh[4][4];
#pragma unroll
            for (int nj = 0; nj < 4; nj++)
                ldsm_x4(bqh[nj], st + 2 * SLOT_ELEMS + swoff(rb + nj * 16, cb));
            // product 1: Ahi * Whi
#pragma unroll
            for (int mi = 0; mi < 2; mi++)
#pragma unroll
                for (int ni = 0; ni < 8; ni++)
                    mma16816(acc[mi][ni], afh[mi], bqh[ni >> 1][(ni & 1) * 2],
                             bqh[ni >> 1][(ni & 1) * 2 + 1]);
            // product 3: Alo * Whi  (bqh dead afterwards)
#pragma unroll
            for (int mi = 0; mi < 2; mi++)
#pragma unroll
                for (int ni = 0; ni < 8; ni++)
                    mma16816(acc[mi][ni], afl[mi], bqh[ni >> 1][(ni & 1) * 2],
                             bqh[ni >> 1][(ni & 1) * 2 + 1]);
            // product 2: Ahi * Wlo
            uint32_t bql[4][4];
#pragma unroll
            for (int nj = 0; nj < 4; nj++)
                ldsm_x4(bql[nj], st + 3 * SLOT_ELEMS + swoff(rb + nj * 16, cb));
#pragma unroll
            for (int mi = 0; mi < 2; mi++)
#pragma unroll
                for (int ni = 0; ni < 8; ni++)
                    mma16816(acc[mi][ni], afh[mi], bql[ni >> 1][(ni & 1) * 2],
                             bql[ni >> 1][(ni & 1) * 2 + 1]);
        }
    }

    // ---------------- epilogue: (a,v) -> in-chunk prefix (P,Q) ----------------
    __syncthreads();            // mainloop fully done; smem now reusable
    float2* av_sm  = reinterpret_cast<float2*>(smem);            // [128][64] 64KB
    float2* red_sm = reinterpret_cast<float2*>(smem) + 128 * 64; // [4][64]  2KB

    // phase 1: fragments -> (a,v) staged in SMEM
    const int tig = lane & 3;
    const int grp = lane >> 2;
#pragma unroll
    for (int mi = 0; mi < 2; mi++) {
        int s0 = wm * 32 + mi * 16 + grp;              // local row 0..127
#pragma unroll
        for (int ni = 0; ni < 8; ni++) {
            int col = n0 + wn * 64 + ni * 8 + tig * 2; // global interleaved col
            int chl = wn * 32 + ni * 4 + tig;          // local channel 0..63
            float bg = bc[col];
            float bh = bc[col + 1];
            av_sm[s0 * 64 + chl] =
                av_from(acc[mi][ni][0] + bg, acc[mi][ni][1] + bh);
            av_sm[(s0 + 8) * 64 + chl] =
                av_from(acc[mi][ni][2] + bg, acc[mi][ni][3] + bh);
        }
    }
    __syncthreads();

    const int g = tid >> 6;          // group 0..3 (32 rows each)
    const int d = tid & 63;          // local channel
    // phase 2: local prefix scan within group, stored in-place
    {
        float A = 1.0f, V = 0.0f;
#pragma unroll 8
        for (int s = g * 32; s < g * 32 + 32; s++) {
            float2 t = av_sm[s * 64 + d];
            V = fmaf(t.x, V, t.y);
            A *= t.x;
            av_sm[s * 64 + d] = make_float2(A, V);
        }
        red_sm[g * 64 + d] = make_float2(A, V);
    }
    __syncthreads();
    // phase 3: apply group-prefix offset; write (P,Q) + chunk aggregate
    {
        float Ap = 1.0f, Vp = 0.0f;
#pragma unroll
        for (int q = 0; q < 3; q++) {
            if (q < g) {
                float2 t = red_sm[q * 64 + d];
                Vp = fmaf(t.x, Vp, t.y);
                Ap *= t.x;
            }
        }
        const int dg = (n0 >> 1) + d;          // global channel
        float P = 1.0f, Q = 0.0f;
#pragma unroll 8
        for (int s = g * 32; s < g * 32 + 32; s++) {
            float2 t = av_sm[s * 64 + d];
            P = t.x * Ap;
            Q = fmaf(t.x, Vp, t.y);
            g_av[(size_t)(m0 + s) * 256 + dg] = make_float2(P, Q);
        }
        if (g == 3) {
            const int b  = m0 >> 13;
            const int ck = (m0 >> 7) & 63;
            g_agg[(b * NCH + ck) * 256 + dg] = make_float2(P, Q);
        }
    }
}

// -------------------- chunked scan -----------------------------------------
// combine: sequential over NCH chunk aggregates -> per-chunk starting h0.
__global__ void scan_combine() {
    int b = blockIdx.x, d = threadIdx.x;
    float h = 0.5f;
    for (int c0 = 0; c0 < NCH; c0 += 8) {
        float2 t[8];
#pragma unroll
        for (int j = 0; j < 8; j++)
            t[j] = g_agg[(b * NCH + c0 + j) * 256 + d];
#pragma unroll
        for (int j = 0; j < 8; j++) {
            g_h0[(b * NCH + c0 + j) * 256 + d] = h;
            h = fmaf(t[j].x, h, t[j].y);
        }
    }
}

// pass3 layer 0 (elementwise): h = P*h0 + Q; write out0 as bf16 hi/lo split;
// last row -> h[0] tail of d_out
__global__ void scan_pass3_l0(float* __restrict__ dout) {
    int b = blockIdx.x, ch = blockIdx.y, d = threadIdx.x;
    float h0v = g_h0[(b * NCH + ch) * 256 + d];
    size_t row0 = (size_t)b * SEQ + ch * CHLEN;
    float hlast = 0.0f;
#pragma unroll 8
    for (int s = 0; s < CHLEN; s++) {
        size_t idx = (row0 + s) * 256 + d;
        float2 t = g_av[idx];
        float h = fmaf(t.x, h0v, t.y);
        __nv_bfloat16 hi = __float2bfloat16(h);
        g_xhi[idx] = hi;
        g_xlo[idx] = __float2bfloat16(h - __bfloat162float(hi));
        if (s == CHLEN - 1) hlast = h;
    }
    if (ch == NCH - 1) dout[OUT1_ELEMS + b * 256 + d] = hlast;
}

// pass3 layer 1 (elementwise): write out1 fp32; last row -> h[1] tail
__global__ void scan_pass3_l1(float* __restrict__ dout) {
    int b = blockIdx.x, ch = blockIdx.y, d = threadIdx.x;
    float h0v = g_h0[(b * NCH + ch) * 256 + d];
    size_t row0 = (size_t)b * SEQ + ch * CHLEN;
    float hlast = 0.0f;
#pragma unroll 8
    for (int s = 0; s < CHLEN; s++) {
        size_t idx = (row0 + s) * 256 + d;
        float2 t = g_av[idx];
        float h = fmaf(t.x, h0v, t.y);
        dout[idx] = h;
        if (s == CHLEN - 1) hlast = h;
    }
    if (ch == NCH - 1) dout[OUT1_ELEMS + 2048 + b * 256 + d] = hlast;
}

// -------------------- launch -----------------------------------------------
extern "C" void kernel_launch(void* const* d_in, const int* in_sizes, int n_in,
                              void* d_out, int out_size) {
    const float* x  = (const float*)d_in[0];
    const float* W0 = (const float*)d_in[1];
    const float* b0 = (const float*)d_in[2];
    const float* W1 = (const float*)d_in[3];
    const float* b1 = (const float*)d_in[4];
    float* out = (float*)d_out;

    cudaFuncSetAttribute(gemm_kernel,
                         cudaFuncAttributeMaxDynamicSharedMemorySize, SMEM_BYTES);

    dim3 ggrid(4, 512);        // x = N blocks (fast) so A-panel reuse hits L2
    dim3 sgrid(BATCH, NCH);

    convert_inputs<<<17412, 256>>>(x, W0, W1, b0, b1);

    gemm_kernel<<<ggrid, 256, SMEM_BYTES>>>(0);   // includes prefix pass1
    scan_combine<<<BATCH, 256>>>();
    scan_pass3_l0<<<sgrid, 256>>>(out);

    gemm_kernel<<<ggrid, 256, SMEM_BYTES>>>(1);   // includes prefix pass1
    scan_combine<<<BATCH, 256>>>();
    scan_pass3_l1<<<sgrid, 256>>>(out);
}